// round 1
// baseline (speedup 1.0000x reference)
#include <cuda_runtime.h>

#define NROWS 16384
#define KDIM  16

// ---------------- device scratch (no allocation allowed) ----------------
__device__ float g_CT[KDIM * NROWS];   // C transposed: g_CT[k][j]
__device__ float g_deg[NROWS];         // row degrees
__device__ float g_S;                  // sum(C * (adj @ C))
__device__ float g_m2;                 // sum(deg) = 2m
__device__ float g_dC[KDIM];           // deg @ C
__device__ float g_cs[KDIM];           // column sums of C

// ---------------- packed f32x2 helpers (Blackwell FFMA2) ----------------
__device__ __forceinline__ void fma2(unsigned long long &acc,
                                     unsigned long long a,
                                     unsigned long long b) {
    asm("fma.rn.f32x2 %0, %1, %2, %0;" : "+l"(acc) : "l"(a), "l"(b));
}
__device__ __forceinline__ void add2(unsigned long long &acc, unsigned long long a) {
    asm("add.rn.f32x2 %0, %0, %1;" : "+l"(acc) : "l"(a));
}
__device__ __forceinline__ float2 unpack2(unsigned long long v) {
    unsigned int lo, hi;
    asm("mov.b64 {%0, %1}, %2;" : "=r"(lo), "=r"(hi) : "l"(v));
    return make_float2(__uint_as_float(lo), __uint_as_float(hi));
}

// ---------------- kernel 0: zero accumulators ----------------
__global__ void zero_kernel() {
    int t = threadIdx.x;
    if (t == 0) { g_S = 0.0f; g_m2 = 0.0f; }
    if (t < KDIM) { g_dC[t] = 0.0f; g_cs[t] = 0.0f; }
}

// ---------------- kernel 1: transpose C (1 MB) ----------------
__global__ void transpose_kernel(const float* __restrict__ C) {
    int j = blockIdx.x * blockDim.x + threadIdx.x;   // 0..NROWS-1
    if (j >= NROWS) return;
#pragma unroll
    for (int q = 0; q < 4; q++) {
        float4 v = *reinterpret_cast<const float4*>(C + (size_t)j * KDIM + q * 4);
        g_CT[(q * 4 + 0) * NROWS + j] = v.x;
        g_CT[(q * 4 + 1) * NROWS + j] = v.y;
        g_CT[(q * 4 + 2) * NROWS + j] = v.z;
        g_CT[(q * 4 + 3) * NROWS + j] = v.w;
    }
}

// ---------------- kernel 2: main pass over adj (1.07 GB) ----------------
// Grid: 256 CTAs x 256 threads. CTA b owns rows [b*64, b*64+64).
// Warp w owns 8 rows; lane = (jl = lane&7 -> 4 j-columns, kg = lane>>3 -> 4 k's).
// Each lane: acc[r][k] (float2 over even/odd j) accumulates adj*CT; dacc[r] accumulates deg.
__global__ __launch_bounds__(256) void main_kernel(const float* __restrict__ adj,
                                                   const float* __restrict__ C) {
    const int lane = threadIdx.x & 31;
    const int wid  = threadIdx.x >> 5;
    const int jl   = lane & 7;
    const int kg   = lane >> 3;
    const int row0 = blockIdx.x * 64 + wid * 8;
    const int jc   = jl * 4;

    unsigned long long acc[8][4];
    unsigned long long dacc[8];
#pragma unroll
    for (int r = 0; r < 8; r++) {
        dacc[r] = 0ULL;
#pragma unroll
        for (int k = 0; k < 4; k++) acc[r][k] = 0ULL;
    }

    const float* aBase = adj  + (size_t)row0 * NROWS + jc;
    const float* cBase = g_CT + (size_t)(kg * 4) * NROWS + jc;

    for (int it = 0; it < NROWS / 32; ++it) {
        const int off = it * 32;
        ulonglong2 a[8], c[4];
#pragma unroll
        for (int r = 0; r < 8; r++)
            a[r] = *reinterpret_cast<const ulonglong2*>(aBase + (size_t)r * NROWS + off);
#pragma unroll
        for (int k = 0; k < 4; k++)
            c[k] = *reinterpret_cast<const ulonglong2*>(cBase + (size_t)k * NROWS + off);
#pragma unroll
        for (int r = 0; r < 8; r++) {
#pragma unroll
            for (int k = 0; k < 4; k++) {
                fma2(acc[r][k], a[r].x, c[k].x);   // cols jc+0, jc+1
                fma2(acc[r][k], a[r].y, c[k].y);   // cols jc+2, jc+3
            }
            add2(dacc[r], a[r].x);
            add2(dacc[r], a[r].y);
        }
    }

    // Epilogue: per row, s = sum_k C[row][k] * AC[row][k]; warp-reduce s and deg.
    float sWarp = 0.0f;
#pragma unroll
    for (int r = 0; r < 8; r++) {
        const int row = row0 + r;
        float4 cm = *reinterpret_cast<const float4*>(C + (size_t)row * KDIM + kg * 4);
        float2 t0 = unpack2(acc[r][0]);
        float2 t1 = unpack2(acc[r][1]);
        float2 t2 = unpack2(acc[r][2]);
        float2 t3 = unpack2(acc[r][3]);
        float s = (t0.x + t0.y) * cm.x + (t1.x + t1.y) * cm.y +
                  (t2.x + t2.y) * cm.z + (t3.x + t3.y) * cm.w;
        float2 dt = unpack2(dacc[r]);
        float dg = dt.x + dt.y;
#pragma unroll
        for (int o = 16; o > 0; o >>= 1) {
            s  += __shfl_xor_sync(0xffffffffu, s,  o);
            dg += __shfl_xor_sync(0xffffffffu, dg, o);
        }
        if (lane == 0) {
            g_deg[row] = dg * 0.25f;   // kg 4-way duplication of adj loads
            sWarp += s;
        }
    }
    if (lane == 0) atomicAdd(&g_S, sWarp);
}

// ---------------- kernel 3: stats over deg and C ----------------
__global__ __launch_bounds__(256) void stats_kernel(const float* __restrict__ C) {
    const int gtid   = blockIdx.x * 256 + threadIdx.x;
    const int stride = gridDim.x * 256;
    float m_l = 0.0f;
    float dc[KDIM], cs[KDIM];
#pragma unroll
    for (int k = 0; k < KDIM; k++) { dc[k] = 0.0f; cs[k] = 0.0f; }

    for (int i = gtid; i < NROWS; i += stride) {
        float d = g_deg[i];
        m_l += d;
#pragma unroll
        for (int q = 0; q < 4; q++) {
            float4 v = *reinterpret_cast<const float4*>(C + (size_t)i * KDIM + q * 4);
            dc[q * 4 + 0] += d * v.x;  cs[q * 4 + 0] += v.x;
            dc[q * 4 + 1] += d * v.y;  cs[q * 4 + 1] += v.y;
            dc[q * 4 + 2] += d * v.z;  cs[q * 4 + 2] += v.z;
            dc[q * 4 + 3] += d * v.w;  cs[q * 4 + 3] += v.w;
        }
    }
#pragma unroll
    for (int o = 16; o > 0; o >>= 1) {
        m_l += __shfl_xor_sync(0xffffffffu, m_l, o);
#pragma unroll
        for (int k = 0; k < KDIM; k++) {
            dc[k] += __shfl_xor_sync(0xffffffffu, dc[k], o);
            cs[k] += __shfl_xor_sync(0xffffffffu, cs[k], o);
        }
    }
    if ((threadIdx.x & 31) == 0) {
        atomicAdd(&g_m2, m_l);
#pragma unroll
        for (int k = 0; k < KDIM; k++) {
            atomicAdd(&g_dC[k], dc[k]);
            atomicAdd(&g_cs[k], cs[k]);
        }
    }
}

// ---------------- kernel 4: finalize (double precision) ----------------
__global__ void final_kernel(const float* __restrict__ beta, float* __restrict__ out) {
    double two_m = (double)g_m2;          // 2m = sum(deg)
    double S     = (double)g_S;
    double dc2 = 0.0, coll = 0.0;
#pragma unroll
    for (int k = 0; k < KDIM; k++) {
        double d = (double)g_dC[k];
        dc2 += d * d;
        coll += fabs((double)g_cs[k] - 1.0);
    }
    double modularity = S - dc2 / two_m;
    double mod_loss   = -modularity / two_m;
    double collapse   = (4.0 / (double)NROWS) * coll;   // sqrt(16)=4
    out[0] = (float)(mod_loss + (double)beta[0] * collapse);
}

// ---------------- launch ----------------
extern "C" void kernel_launch(void* const* d_in, const int* in_sizes, int n_in,
                              void* d_out, int out_size) {
    const float* C    = (const float*)d_in[0];
    // d_in[1] is X — unused by the reference loss.
    const float* adj  = (const float*)d_in[2];
    const float* beta = (const float*)d_in[3];
    float* out = (float*)d_out;

    zero_kernel<<<1, 64>>>();
    transpose_kernel<<<NROWS / 256, 256>>>(C);
    main_kernel<<<NROWS / 64, 256>>>(adj, C);
    stats_kernel<<<32, 256>>>(C);
    final_kernel<<<1, 1>>>(beta, out);
}

// round 3
// speedup vs baseline: 2.4074x; 2.4074x over previous
#include <cuda_runtime.h>
#include <cstdint>

#define NROWS 16384
#define KDIM  16
#define NJ    (NROWS / 32)      // 512 column stripes of 32
#define RPB   32                // rows per work block
#define NBLK  (NROWS / RPB)     // 512 work blocks
#define NCTA  296               // persistent CTAs (2 per SM)

// ---------------- device scratch ----------------
__device__ float g_CT[KDIM * NROWS];   // C transposed: g_CT[k][j]
__device__ float g_deg[NROWS];
__device__ float g_S;
__device__ unsigned int g_work;

// ---------------- packed f32x2 helpers (Blackwell FFMA2) ----------------
__device__ __forceinline__ void fma2(unsigned long long &acc,
                                     unsigned long long a,
                                     unsigned long long b) {
    asm("fma.rn.f32x2 %0, %1, %2, %0;" : "+l"(acc) : "l"(a), "l"(b));
}
__device__ __forceinline__ void add2(unsigned long long &acc, unsigned long long a) {
    asm("add.rn.f32x2 %0, %0, %1;" : "+l"(acc) : "l"(a));
}
__device__ __forceinline__ float2 unpack2(unsigned long long v) {
    unsigned int lo, hi;
    asm("mov.b64 {%0, %1}, %2;" : "=r"(lo), "=r"(hi) : "l"(v));
    return make_float2(__uint_as_float(lo), __uint_as_float(hi));
}
__device__ __forceinline__ unsigned smem_u32(const void* p) {
    return (unsigned)__cvta_generic_to_shared(p);
}
__device__ __forceinline__ void cpasync16(unsigned dst, const float* src) {
    asm volatile("cp.async.ca.shared.global [%0], [%1], 16;" :: "r"(dst), "l"(src) : "memory");
}
__device__ __forceinline__ void cpcommit() { asm volatile("cp.async.commit_group;" ::: "memory"); }
__device__ __forceinline__ void cpwait1()  { asm volatile("cp.async.wait_group 1;" ::: "memory"); }

// ---------------- kernel 0: zero + transpose C ----------------
__global__ void prep_kernel(const float* __restrict__ C) {
    if (blockIdx.x == 0 && threadIdx.x == 0) { g_S = 0.0f; g_work = 0u; }
    int j = blockIdx.x * blockDim.x + threadIdx.x;
    if (j >= NROWS) return;
#pragma unroll
    for (int q = 0; q < 4; q++) {
        float4 v = *reinterpret_cast<const float4*>(C + (size_t)j * KDIM + q * 4);
        g_CT[(q * 4 + 0) * NROWS + j] = v.x;
        g_CT[(q * 4 + 1) * NROWS + j] = v.y;
        g_CT[(q * 4 + 2) * NROWS + j] = v.z;
        g_CT[(q * 4 + 3) * NROWS + j] = v.w;
    }
}

// ---------------- kernel 1: main pass over adj (1.07 GB) ----------------
// Persistent CTAs, 256 threads (8 warps). Work block = 32 rows (4 per warp).
// Lane: jl = lane&7 -> 4 j-columns; kg = lane>>3 -> 4 of the 16 k's.
// CT stripe tiles (16x32 f32 = 2KB) triple-buffered in shared via cp.async.
// adj rows prefetched 2 stripes ahead in registers (3 rolling slots).
__global__ __launch_bounds__(256, 2) void main_kernel(const float* __restrict__ adj,
                                                      const float* __restrict__ C) {
    __shared__ __align__(16) float tile[3][KDIM * 32];
    __shared__ unsigned s_blk;
    const int tid  = threadIdx.x;
    const int lane = tid & 31;
    const int wid  = tid >> 5;
    const int jl   = lane & 7;
    const int kg   = lane >> 3;
    const int tk   = tid >> 3;          // 0..31 (only <16 used for tile copy)
    const int tp   = tid & 7;

    for (;;) {
        if (tid == 0) s_blk = atomicAdd(&g_work, 1u);
        __syncthreads();
        const unsigned blk = s_blk;
        __syncthreads();
        if (blk >= NBLK) break;

        const int row0 = blk * RPB + wid * 4;
        const float* aBase = adj + (size_t)row0 * NROWS + jl * 4;

        // --- prologue: CT tiles for stripes 0,1 via cp.async (2 groups) ---
        if (tid < 128) {
            cpasync16(smem_u32(&tile[0][tk * 32 + tp * 4]),
                      g_CT + (size_t)tk * NROWS + tp * 4);
        }
        cpcommit();
        if (tid < 128) {
            cpasync16(smem_u32(&tile[1][tk * 32 + tp * 4]),
                      g_CT + (size_t)tk * NROWS + 32 + tp * 4);
        }
        cpcommit();

        // --- prologue: adj stripes 0,1 into register slots 0,1 ---
        ulonglong2 aS[3][4];
#pragma unroll
        for (int r = 0; r < 4; r++) {
            aS[0][r] = *reinterpret_cast<const ulonglong2*>(aBase + (size_t)r * NROWS);
            aS[1][r] = *reinterpret_cast<const ulonglong2*>(aBase + (size_t)r * NROWS + 32);
        }

        unsigned long long acc[4][4];
        unsigned long long dacc[4];
#pragma unroll
        for (int r = 0; r < 4; r++) {
            dacc[r] = 0ULL;
#pragma unroll
            for (int k = 0; k < 4; k++) acc[r][k] = 0ULL;
        }

#pragma unroll 3
        for (int it = 0; it < NJ; ++it) {
            cpwait1();            // this thread's copies for tile(it) done
            __syncthreads();      // everyone's copies visible; old buffer free

            // issue CT tile for stripe it+2 into buffer (it+2)%3
            if (it + 2 < NJ) {
                if (tid < 128) {
                    cpasync16(smem_u32(&tile[(it + 2) % 3][tk * 32 + tp * 4]),
                              g_CT + (size_t)tk * NROWS + (size_t)(it + 2) * 32 + tp * 4);
                }
            }
            cpcommit();           // uniform group count even when empty

            // prefetch adj stripe it+2 into slot (it+2)%3
            {
                const int pn = (it + 2 < NJ) ? (it + 2) : 0;
                const int sl = (it + 2) % 3;
#pragma unroll
                for (int r = 0; r < 4; r++)
                    aS[sl][r] = *reinterpret_cast<const ulonglong2*>(
                        aBase + (size_t)r * NROWS + (size_t)pn * 32);
            }

            // compute on slot it%3 with tile[it%3]
            const int cs_ = it % 3;
            const float* tb = &tile[cs_][0];
#pragma unroll
            for (int k = 0; k < 4; k++) {
                ulonglong2 c = *reinterpret_cast<const ulonglong2*>(
                    tb + (kg * 4 + k) * 32 + jl * 4);
#pragma unroll
                for (int r = 0; r < 4; r++) {
                    fma2(acc[r][k], aS[cs_][r].x, c.x);
                    fma2(acc[r][k], aS[cs_][r].y, c.y);
                }
            }
#pragma unroll
            for (int r = 0; r < 4; r++) {
                add2(dacc[r], aS[cs_][r].x);
                add2(dacc[r], aS[cs_][r].y);
            }
        }

        // --- epilogue: per-row dot with C, warp reduce ---
        float sW = 0.0f;
#pragma unroll
        for (int r = 0; r < 4; r++) {
            const int row = row0 + r;
            float4 cm = *reinterpret_cast<const float4*>(C + (size_t)row * KDIM + kg * 4);
            float2 t0 = unpack2(acc[r][0]);
            float2 t1 = unpack2(acc[r][1]);
            float2 t2 = unpack2(acc[r][2]);
            float2 t3 = unpack2(acc[r][3]);
            float s = (t0.x + t0.y) * cm.x + (t1.x + t1.y) * cm.y +
                      (t2.x + t2.y) * cm.z + (t3.x + t3.y) * cm.w;
            float2 dt = unpack2(dacc[r]);
            float dg = dt.x + dt.y;
#pragma unroll
            for (int o = 16; o > 0; o >>= 1) {
                s  += __shfl_xor_sync(0xffffffffu, s,  o);
                dg += __shfl_xor_sync(0xffffffffu, dg, o);
            }
            if (lane == 0) {
                g_deg[row] = dg * 0.25f;   // kg 4-way adj duplication
                sW += s;
            }
        }
        if (lane == 0) atomicAdd(&g_S, sW);
    }
}

// ---------------- kernel 2: stats + finalize (single CTA) ----------------
__global__ __launch_bounds__(256) void finish_kernel(const float* __restrict__ C,
                                                     const float* __restrict__ beta,
                                                     float* __restrict__ out) {
    const int tid = threadIdx.x;
    float m_l = 0.0f;
    float dc[KDIM], cs[KDIM];
#pragma unroll
    for (int k = 0; k < KDIM; k++) { dc[k] = 0.0f; cs[k] = 0.0f; }

    for (int i = tid; i < NROWS; i += 256) {
        float d = g_deg[i];
        m_l += d;
#pragma unroll
        for (int q = 0; q < 4; q++) {
            float4 v = *reinterpret_cast<const float4*>(C + (size_t)i * KDIM + q * 4);
            dc[q * 4 + 0] += d * v.x;  cs[q * 4 + 0] += v.x;
            dc[q * 4 + 1] += d * v.y;  cs[q * 4 + 1] += v.y;
            dc[q * 4 + 2] += d * v.z;  cs[q * 4 + 2] += v.z;
            dc[q * 4 + 3] += d * v.w;  cs[q * 4 + 3] += v.w;
        }
    }
    // warp reduce
#pragma unroll
    for (int o = 16; o > 0; o >>= 1) {
        m_l += __shfl_xor_sync(0xffffffffu, m_l, o);
#pragma unroll
        for (int k = 0; k < KDIM; k++) {
            dc[k] += __shfl_xor_sync(0xffffffffu, dc[k], o);
            cs[k] += __shfl_xor_sync(0xffffffffu, cs[k], o);
        }
    }
    __shared__ float red[8][33];
    const int wid = tid >> 5;
    if ((tid & 31) == 0) {
        red[wid][0] = m_l;
#pragma unroll
        for (int k = 0; k < KDIM; k++) { red[wid][1 + k] = dc[k]; red[wid][17 + k] = cs[k]; }
    }
    __syncthreads();
    if (tid == 0) {
        double m = 0.0, dcd[KDIM], csd[KDIM];
#pragma unroll
        for (int k = 0; k < KDIM; k++) { dcd[k] = 0.0; csd[k] = 0.0; }
        for (int w = 0; w < 8; w++) {
            m += (double)red[w][0];
#pragma unroll
            for (int k = 0; k < KDIM; k++) {
                dcd[k] += (double)red[w][1 + k];
                csd[k] += (double)red[w][17 + k];
            }
        }
        double two_m = m;
        double S = (double)g_S;
        double dc2 = 0.0, coll = 0.0;
#pragma unroll
        for (int k = 0; k < KDIM; k++) {
            dc2  += dcd[k] * dcd[k];
            coll += fabs(csd[k] - 1.0);
        }
        double modularity = S - dc2 / two_m;
        double mod_loss   = -modularity / two_m;
        double collapse   = (4.0 / (double)NROWS) * coll;   // sqrt(16)=4
        out[0] = (float)(mod_loss + (double)beta[0] * collapse);
    }
}

// ---------------- kernel 3: padding no-op (keeps main_kernel at ncu's -s 5 slot) ----------------
__global__ void noop_kernel() {}

// ---------------- launch ----------------
extern "C" void kernel_launch(void* const* d_in, const int* in_sizes, int n_in,
                              void* d_out, int out_size) {
    const float* C    = (const float*)d_in[0];
    // d_in[1] is X — unused by the reference loss.
    const float* adj  = (const float*)d_in[2];
    const float* beta = (const float*)d_in[3];
    float* out = (float*)d_out;

    prep_kernel<<<NROWS / 256, 256>>>(C);       // launch 0
    main_kernel<<<NCTA, 256>>>(adj, C);         // launch 1  (5 mod 4 == 1)
    finish_kernel<<<1, 256>>>(C, beta, out);    // launch 2
    noop_kernel<<<1, 32>>>();                   // launch 3
}

// round 4
// speedup vs baseline: 3.1794x; 1.3206x over previous
#include <cuda_runtime.h>
#include <cstdint>

#define NROWS 16384
#define KDIM  16
#define SPU   128               // stripes (32 cols) per work unit
#define NUNIT 2048              // 512 row-blocks x 4 j-quarters
#define NCTA  304               // persistent CTAs (2 per SM on 152 SMs)

// ---------------- device scratch ----------------
__device__ float g_CT[KDIM * NROWS];   // C transposed: g_CT[k][j]
__device__ float g_deg[NROWS];
__device__ float g_S;
__device__ float g_m2;
__device__ float g_dC[KDIM];
__device__ float g_cs[KDIM];
__device__ unsigned int g_work;

// ---------------- packed f32x2 helpers (Blackwell FFMA2) ----------------
__device__ __forceinline__ void fma2(unsigned long long &acc,
                                     unsigned long long a,
                                     unsigned long long b) {
    asm("fma.rn.f32x2 %0, %1, %2, %0;" : "+l"(acc) : "l"(a), "l"(b));
}
__device__ __forceinline__ void add2(unsigned long long &acc, unsigned long long a) {
    asm("add.rn.f32x2 %0, %0, %1;" : "+l"(acc) : "l"(a));
}
__device__ __forceinline__ float2 unpack2(unsigned long long v) {
    unsigned int lo, hi;
    asm("mov.b64 {%0, %1}, %2;" : "=r"(lo), "=r"(hi) : "l"(v));
    return make_float2(__uint_as_float(lo), __uint_as_float(hi));
}

// ---------------- kernel 0: zero scratch + transpose C ----------------
__global__ void prep_kernel(const float* __restrict__ C) {
    int j = blockIdx.x * blockDim.x + threadIdx.x;   // 0..NROWS-1 (64x256)
    if (j == 0) { g_S = 0.0f; g_m2 = 0.0f; g_work = 0u; }
    if (j < KDIM) { g_dC[j] = 0.0f; g_cs[j] = 0.0f; }
    if (j >= NROWS) return;
    g_deg[j] = 0.0f;
#pragma unroll
    for (int q = 0; q < 4; q++) {
        float4 v = *reinterpret_cast<const float4*>(C + (size_t)j * KDIM + q * 4);
        g_CT[(q * 4 + 0) * NROWS + j] = v.x;
        g_CT[(q * 4 + 1) * NROWS + j] = v.y;
        g_CT[(q * 4 + 2) * NROWS + j] = v.z;
        g_CT[(q * 4 + 3) * NROWS + j] = v.w;
    }
}

// ---------------- kernel 1: main pass over adj (1.07 GB) ----------------
// Persistent CTAs, 256 threads (8 warps), 2 CTAs/SM. No smem, no barriers in
// the hot loop: each warp is an independent depth-2 register pipeline.
// Work unit = (32 rows, 128 stripes of 32 cols). Warp owns 4 rows.
// Lane: jl = lane&7 -> 4 j-cols, kg = lane>>3 -> 4 of the 16 k's.
__global__ __launch_bounds__(256, 2) void main_kernel(const float* __restrict__ adj,
                                                      const float* __restrict__ C) {
    __shared__ unsigned s_blk;
    const int tid  = threadIdx.x;
    const int lane = tid & 31;
    const int wid  = tid >> 5;
    const int jl   = lane & 7;
    const int kg   = lane >> 3;

    for (;;) {
        if (tid == 0) s_blk = atomicAdd(&g_work, 1u);
        __syncthreads();
        const unsigned blk = s_blk;
        __syncthreads();
        if (blk >= NUNIT) break;

        const int rowblk = blk >> 2;
        const int jq     = blk & 3;
        const int row0   = rowblk * 32 + wid * 4;
        const int col0   = jq * (SPU * 32) + jl * 4;

        const float* aB = adj  + (size_t)row0 * NROWS + col0;
        const float* cB = g_CT + (size_t)(kg * 4) * NROWS + col0;

        // prologue: stripes 0,1 into both pipeline slots
        ulonglong2 aS[2][4], cS[2][4];
#pragma unroll
        for (int r = 0; r < 4; r++) {
            aS[0][r] = *reinterpret_cast<const ulonglong2*>(aB + (size_t)r * NROWS);
            aS[1][r] = *reinterpret_cast<const ulonglong2*>(aB + (size_t)r * NROWS + 32);
        }
#pragma unroll
        for (int k = 0; k < 4; k++) {
            cS[0][k] = *reinterpret_cast<const ulonglong2*>(cB + (size_t)k * NROWS);
            cS[1][k] = *reinterpret_cast<const ulonglong2*>(cB + (size_t)k * NROWS + 32);
        }

        unsigned long long acc[4][4];
        unsigned long long dacc[4];
#pragma unroll
        for (int r = 0; r < 4; r++) {
            dacc[r] = 0ULL;
#pragma unroll
            for (int k = 0; k < 4; k++) acc[r][k] = 0ULL;
        }

#pragma unroll 2
        for (int it = 0; it < SPU; ++it) {
            const int p = it & 1;
            // compute on slot p (stripe it)
#pragma unroll
            for (int r = 0; r < 4; r++) {
#pragma unroll
                for (int k = 0; k < 4; k++) {
                    fma2(acc[r][k], aS[p][r].x, cS[p][k].x);
                    fma2(acc[r][k], aS[p][r].y, cS[p][k].y);
                }
                add2(dacc[r], aS[p][r].x);
                add2(dacc[r], aS[p][r].y);
            }
            // refill slot p with stripe it+2
            if (it + 2 < SPU) {
                const size_t off = (size_t)(it + 2) * 32;
#pragma unroll
                for (int r = 0; r < 4; r++)
                    aS[p][r] = *reinterpret_cast<const ulonglong2*>(aB + (size_t)r * NROWS + off);
#pragma unroll
                for (int k = 0; k < 4; k++)
                    cS[p][k] = *reinterpret_cast<const ulonglong2*>(cB + (size_t)k * NROWS + off);
            }
        }

        // epilogue: per-row dot with C, warp reduce, atomics
        float sW = 0.0f;
#pragma unroll
        for (int r = 0; r < 4; r++) {
            const int row = row0 + r;
            float4 cm = *reinterpret_cast<const float4*>(C + (size_t)row * KDIM + kg * 4);
            float2 t0 = unpack2(acc[r][0]);
            float2 t1 = unpack2(acc[r][1]);
            float2 t2 = unpack2(acc[r][2]);
            float2 t3 = unpack2(acc[r][3]);
            float s = (t0.x + t0.y) * cm.x + (t1.x + t1.y) * cm.y +
                      (t2.x + t2.y) * cm.z + (t3.x + t3.y) * cm.w;
            float2 dt = unpack2(dacc[r]);
            float dg = dt.x + dt.y;
#pragma unroll
            for (int o = 16; o > 0; o >>= 1) {
                s  += __shfl_xor_sync(0xffffffffu, s,  o);
                dg += __shfl_xor_sync(0xffffffffu, dg, o);
            }
            if (lane == 0) {
                atomicAdd(&g_deg[row], dg * 0.25f);   // kg 4-way adj duplication
                sW += s;
            }
        }
        if (lane == 0) atomicAdd(&g_S, sW);
    }
}

// ---------------- kernel 2: stats over deg and C ----------------
__global__ __launch_bounds__(256) void stats_kernel(const float* __restrict__ C) {
    const int gtid   = blockIdx.x * 256 + threadIdx.x;
    const int stride = gridDim.x * 256;
    float m_l = 0.0f;
    float dc[KDIM], cs[KDIM];
#pragma unroll
    for (int k = 0; k < KDIM; k++) { dc[k] = 0.0f; cs[k] = 0.0f; }

    for (int i = gtid; i < NROWS; i += stride) {
        float d = g_deg[i];
        m_l += d;
#pragma unroll
        for (int q = 0; q < 4; q++) {
            float4 v = *reinterpret_cast<const float4*>(C + (size_t)i * KDIM + q * 4);
            dc[q * 4 + 0] += d * v.x;  cs[q * 4 + 0] += v.x;
            dc[q * 4 + 1] += d * v.y;  cs[q * 4 + 1] += v.y;
            dc[q * 4 + 2] += d * v.z;  cs[q * 4 + 2] += v.z;
            dc[q * 4 + 3] += d * v.w;  cs[q * 4 + 3] += v.w;
        }
    }
#pragma unroll
    for (int o = 16; o > 0; o >>= 1) {
        m_l += __shfl_xor_sync(0xffffffffu, m_l, o);
#pragma unroll
        for (int k = 0; k < KDIM; k++) {
            dc[k] += __shfl_xor_sync(0xffffffffu, dc[k], o);
            cs[k] += __shfl_xor_sync(0xffffffffu, cs[k], o);
        }
    }
    if ((threadIdx.x & 31) == 0) {
        atomicAdd(&g_m2, m_l);
#pragma unroll
        for (int k = 0; k < KDIM; k++) {
            atomicAdd(&g_dC[k], dc[k]);
            atomicAdd(&g_cs[k], cs[k]);
        }
    }
}

// ---------------- kernel 3: finalize (double precision) ----------------
__global__ void final_kernel(const float* __restrict__ beta, float* __restrict__ out) {
    double two_m = (double)g_m2;
    double S     = (double)g_S;
    double dc2 = 0.0, coll = 0.0;
#pragma unroll
    for (int k = 0; k < KDIM; k++) {
        double d = (double)g_dC[k];
        dc2 += d * d;
        coll += fabs((double)g_cs[k] - 1.0);
    }
    double modularity = S - dc2 / two_m;
    double mod_loss   = -modularity / two_m;
    double collapse   = (4.0 / (double)NROWS) * coll;   // sqrt(16)=4
    out[0] = (float)(mod_loss + (double)beta[0] * collapse);
}

// ---------------- padding no-ops (ncu -s 5 alignment: observed offset +2) ----------------
__global__ void pad_kernel() {}

// ---------------- launch ----------------
extern "C" void kernel_launch(void* const* d_in, const int* in_sizes, int n_in,
                              void* d_out, int out_size) {
    const float* C    = (const float*)d_in[0];
    // d_in[1] is X — unused by the reference loss.
    const float* adj  = (const float*)d_in[2];
    const float* beta = (const float*)d_in[3];
    float* out = (float*)d_out;

    prep_kernel<<<NROWS / 256, 256>>>(C);       // idx 0
    pad_kernel<<<1, 32>>>();                    // idx 1
    pad_kernel<<<1, 32>>>();                    // idx 2
    main_kernel<<<NCTA, 256>>>(adj, C);         // idx 3  <- ncu -s 5 (offset +2)
    stats_kernel<<<64, 256>>>(C);               // idx 4
    final_kernel<<<1, 1>>>(beta, out);          // idx 5
}